// round 8
// baseline (speedup 1.0000x reference)
#include <cuda_runtime.h>
#include <math.h>

#define NSWEEPS_MAX 16
#define N 64
#define NH 32
#define NP 32            // packed row-pairs per column
#define FULLMASK 0xffffffffu
#define CONV_TOL 1e-11f  // on max apq^2/(app*aqq) over a sweep

typedef unsigned long long ull;

__device__ __forceinline__ ull pack2(float lo, float hi) {
    ull r; asm("mov.b64 %0, {%1, %2};" : "=l"(r) : "f"(lo), "f"(hi)); return r;
}
__device__ __forceinline__ void unpack2(ull v, float& lo, float& hi) {
    asm("mov.b64 {%0, %1}, %2;" : "=f"(lo), "=f"(hi) : "l"(v));
}
__device__ __forceinline__ ull fma2(ull a, ull b, ull c) {
    ull d; asm("fma.rn.f32x2 %0, %1, %2, %3;" : "=l"(d) : "l"(a), "l"(b), "l"(c));
    return d;
}
__device__ __forceinline__ ull mul2(ull a, ull b) {
    ull d; asm("mul.rn.f32x2 %0, %1, %2;" : "=l"(d) : "l"(a), "l"(b));
    return d;
}
__device__ __forceinline__ float hsum2(ull v) {
    float lo, hi; unpack2(v, lo, hi); return lo + hi;
}

// One WARP per 64x64 SPD matrix. One-sided Jacobi on the columns of A.
// Adaptive sweeps (cap 16): per-warp early exit when the sweep's worst
// apq^2/(app*aqq) < CONV_TOL. Gram fusion: next round's apq is accumulated
// inside the rotation loop on the post-shift columns; app/aqq maintained by
// the exact fp64 update app' = app - t*apq (cancellation-safe), re-synced
// fresh at every sweep start. Circle-method ring tournament.
//   log(A) = sum_k (log l_k / l_k^2) u_k u_k^T,  l_k^2 = |u_k|^2.
__global__ void __launch_bounds__(32, 12)
logeig_onesided_kernel(const float* __restrict__ x, float* __restrict__ out)
{
    __shared__ float U[N][N + 1];
    __shared__ float w[N];

    const int lane = threadIdx.x;
    const size_t base = (size_t)blockIdx.x * (N * N);
    const float* __restrict__ xin = x + base;
    float* __restrict__ o = out + base;

    ull top2[NP], bot2[NP];   // columns in slots (lane) and (32+lane)

    // Load: top2[j] packs rows (2j, 2j+1) of column `lane`
    #pragma unroll
    for (int j = 0; j < NP; ++j) {
        top2[j] = pack2(xin[(2 * j) * N + lane],      xin[(2 * j + 1) * N + lane]);
        bot2[j] = pack2(xin[(2 * j) * N + NH + lane], xin[(2 * j + 1) * N + NH + lane]);
    }

    for (int sweep = 0; sweep < NSWEEPS_MAX; ++sweep) {
        // ---- fresh full Gram of the owned pair at sweep start
        ull sp = 0ull, sx = 0ull, sq = 0ull;
        #pragma unroll
        for (int j = 0; j < NP; ++j) {
            ull t2 = top2[j], b2 = bot2[j];
            sp = fma2(t2, t2, sp);
            sx = fma2(t2, b2, sx);
            sq = fma2(b2, b2, sq);
        }
        double dapp = (double)hsum2(sp);
        float  apq  = hsum2(sx);
        double daqq = (double)hsum2(sq);

        float mr = 0.0f;   // worst relative off-diagonal this sweep
        for (int r = 0; r < N - 1; ++r) {
            float app = (float)dapp, aqq = (float)daqq;
            mr = fmaxf(mr, __fdividef(apq * apq, app * aqq));

            // ---- Jacobi rotation from the 2x2 Gram
            float c = 1.0f, s = 0.0f, t = 0.0f;
            if (fabsf(apq) > 1e-30f) {
                float theta = 0.5f * (aqq - app) / apq;
                t = copysignf(1.0f, theta) /
                    (fabsf(theta) + sqrtf(fmaf(theta, theta, 1.0f)));
                c = rsqrtf(fmaf(t, t, 1.0f));
                s = t * c;
            }
            const ull cc = pack2(c, c);
            const ull ss = pack2(s, s);
            const ull ns = pack2(-s, -s);

            // ---- rotate + ring-shift, fusing next round's apq accumulation
            ull sxn = 0ull;
            #pragma unroll
            for (int j = 0; j < NP; ++j) {
                ull t2 = top2[j], b2 = bot2[j];
                ull rt = fma2(cc, t2, mul2(ns, b2));    // c*top - s*bot
                ull rb = fma2(ss, t2, mul2(cc, b2));    // s*top + c*bot
                ull tsel = (lane == 0) ? rb : rt;
                ull tup  = __shfl_up_sync(FULLMASK, tsel, 1);
                ull ntv  = (lane == 0) ? rt : tup;
                ull bdn  = __shfl_down_sync(FULLMASK, rb, 1);
                ull nbv  = (lane == 31) ? rt : bdn;
                top2[j] = ntv;
                bot2[j] = nbv;
                sxn = fma2(ntv, nbv, sxn);
            }

            // ---- exact norm update in fp64 (cancellation-safe) + shift
            double dapp2 = fma((double)(-t), (double)apq, dapp);
            double daqq2 = fma((double)( t), (double)apq, daqq);
            double nsel = (lane == 0) ? daqq2 : dapp2;
            double nup  = __shfl_up_sync(FULLMASK, nsel, 1);
            dapp = (lane == 0) ? dapp2 : nup;
            double ndn  = __shfl_down_sync(FULLMASK, daqq2, 1);
            daqq = (lane == 31) ? dapp2 : ndn;

            apq = hsum2(sxn);
        }

        // ---- warp-allreduce the sweep's worst off-diagonal; maybe stop
        #pragma unroll
        for (int off = 16; off; off >>= 1)
            mr = fmaxf(mr, __shfl_xor_sync(FULLMASK, mr, off));
        if (mr < CONV_TOL) break;
    }

    // ---- final fresh squared norms -> weights w = log(lambda)/lambda^2
    {
        ull sp = 0ull, sq = 0ull;
        #pragma unroll
        for (int j = 0; j < NP; ++j) {
            sp = fma2(top2[j], top2[j], sp);
            sq = fma2(bot2[j], bot2[j], sq);
        }
        float nt = hsum2(sp);
        float nb = hsum2(sq);
        w[lane]      = 0.5f * logf(fmaxf(nt, 1e-38f)) / nt;
        w[NH + lane] = 0.5f * logf(fmaxf(nb, 1e-38f)) / nb;
    }

    // ---- publish U to shared
    #pragma unroll
    for (int j = 0; j < NP; ++j) {
        float a0, a1, b0, b1;
        unpack2(top2[j], a0, a1);
        unpack2(bot2[j], b0, b1);
        U[2 * j][lane]          = a0;
        U[2 * j + 1][lane]      = a1;
        U[2 * j][NH + lane]     = b0;
        U[2 * j + 1][NH + lane] = b1;
    }
    __syncwarp();

    // ---- out = sum_k w_k u_k u_k^T ; lane computes output columns (2*lane, 2*lane+1)
    #pragma unroll
    for (int j = 0; j < NP; ++j) { top2[j] = 0ull; bot2[j] = 0ull; }
    const int j0 = 2 * lane;
    for (int k = 0; k < N; ++k) {
        float wk = w[k];
        float a0 = wk * U[j0][k];
        float a1 = wk * U[j0 + 1][k];
        ull aa0 = pack2(a0, a0);
        ull aa1 = pack2(a1, a1);
        #pragma unroll
        for (int j = 0; j < NP; ++j) {
            ull vv = pack2(U[2 * j][k], U[2 * j + 1][k]);   // broadcast loads
            top2[j] = fma2(aa0, vv, top2[j]);
            bot2[j] = fma2(aa1, vv, bot2[j]);
        }
    }
    // rows 2j / 2j+1, columns (j0, j0+1) contiguous -> coalesced float2 stores
    #pragma unroll
    for (int j = 0; j < NP; ++j) {
        float t0, t1, b0, b1;
        unpack2(top2[j], t0, t1);
        unpack2(bot2[j], b0, b1);
        *reinterpret_cast<float2*>(o + (2 * j) * N + j0)     = make_float2(t0, b0);
        *reinterpret_cast<float2*>(o + (2 * j + 1) * N + j0) = make_float2(t1, b1);
    }
}

extern "C" void kernel_launch(void* const* d_in, const int* in_sizes, int n_in,
                              void* d_out, int out_size) {
    const float* x = (const float*)d_in[0];
    float* out = (float*)d_out;
    int B = in_sizes[0] / (N * N);   // 8192
    logeig_onesided_kernel<<<B, 32>>>(x, out);
}

// round 10
// speedup vs baseline: 1.5524x; 1.5524x over previous
#include <cuda_runtime.h>
#include <math.h>

#define NSWEEPS_MAX 16
#define N 64
#define NH 32
#define NP 32            // packed row-pairs per column
#define FULLMASK 0xffffffffu
#define CONV_TOL 1e-11f  // on max apq^2/(app*aqq) over a sweep

typedef unsigned long long ull;

__device__ __forceinline__ ull pack2(float lo, float hi) {
    ull r; asm("mov.b64 %0, {%1, %2};" : "=l"(r) : "f"(lo), "f"(hi)); return r;
}
__device__ __forceinline__ void unpack2(ull v, float& lo, float& hi) {
    asm("mov.b64 {%0, %1}, %2;" : "=f"(lo), "=f"(hi) : "l"(v));
}
__device__ __forceinline__ ull fma2(ull a, ull b, ull c) {
    ull d; asm("fma.rn.f32x2 %0, %1, %2, %3;" : "=l"(d) : "l"(a), "l"(b), "l"(c));
    return d;
}
__device__ __forceinline__ ull mul2(ull a, ull b) {
    ull d; asm("mul.rn.f32x2 %0, %1, %2;" : "=l"(d) : "l"(a), "l"(b));
    return d;
}
__device__ __forceinline__ float hsum2(ull v) {
    float lo, hi; unpack2(v, lo, hi); return lo + hi;
}

// One WARP per 64x64 SPD matrix. One-sided Jacobi on the columns of A.
// Round-7 structure (fresh 3-dot Gram per round, all fp32, no fused state —
// the round-8 fp64/fusion variant spilled registers and serialized the loop)
// plus a zero-state adaptive exit: track the sweep's worst apq^2/(app*aqq)
// from the already-computed fresh Gram, warp-allreduce once per sweep, break
// below CONV_TOL (cap NSWEEPS_MAX == round-7 behavior). Circle-method ring.
//   log(A) = sum_k (log l_k / l_k^2) u_k u_k^T,  l_k^2 = |u_k|^2.
__global__ void __launch_bounds__(32, 12)
logeig_onesided_kernel(const float* __restrict__ x, float* __restrict__ out)
{
    __shared__ float U[N][N + 1];
    __shared__ float w[N];

    const int lane = threadIdx.x;
    const size_t base = (size_t)blockIdx.x * (N * N);
    const float* __restrict__ xin = x + base;
    float* __restrict__ o = out + base;

    ull top2[NP], bot2[NP];   // columns in slots (lane) and (32+lane)

    // Load: top2[j] packs rows (2j, 2j+1) of column `lane`
    #pragma unroll
    for (int j = 0; j < NP; ++j) {
        top2[j] = pack2(xin[(2 * j) * N + lane],      xin[(2 * j + 1) * N + lane]);
        bot2[j] = pack2(xin[(2 * j) * N + NH + lane], xin[(2 * j + 1) * N + NH + lane]);
    }

    for (int sweep = 0; sweep < NSWEEPS_MAX; ++sweep) {
        float mr = 0.0f;   // worst relative off-diagonal seen this sweep
        for (int r = 0; r < N - 1; ++r) {
            // ---- fresh 2x2 Gram block of the owned pair (fused 3-dot)
            ull sp = 0ull, sx = 0ull, sq = 0ull;
            #pragma unroll
            for (int j = 0; j < NP; ++j) {
                ull t2 = top2[j], b2 = bot2[j];
                sp = fma2(t2, t2, sp);
                sx = fma2(t2, b2, sx);
                sq = fma2(b2, b2, sq);
            }
            float app = hsum2(sp);
            float apq = hsum2(sx);
            float aqq = hsum2(sq);

            mr = fmaxf(mr, __fdividef(apq * apq, app * aqq));

            // ---- Jacobi rotation from the Gram block
            float c = 1.0f, s = 0.0f;
            if (fabsf(apq) > 1e-30f) {
                float theta = 0.5f * (aqq - app) / apq;
                float t = copysignf(1.0f, theta) /
                          (fabsf(theta) + sqrtf(fmaf(theta, theta, 1.0f)));
                c = rsqrtf(fmaf(t, t, 1.0f));
                s = t * c;
            }
            const ull cc = pack2(c, c);
            const ull ss = pack2(s, s);
            const ull ns = pack2(-s, -s);

            // ---- rotate the column pair and ring-shift columns across lanes
            // (circle-method tournament, fused). Rows never move.
            #pragma unroll
            for (int j = 0; j < NP; ++j) {
                ull t2 = top2[j], b2 = bot2[j];
                ull rt = fma2(cc, t2, mul2(ns, b2));    // c*top - s*bot
                ull rb = fma2(ss, t2, mul2(cc, b2));    // s*top + c*bot
                ull tsel = (lane == 0) ? rb : rt;
                ull tup  = __shfl_up_sync(FULLMASK, tsel, 1);
                top2[j]  = (lane == 0) ? rt : tup;
                ull bdn  = __shfl_down_sync(FULLMASK, rb, 1);
                bot2[j]  = (lane == 31) ? rt : bdn;
            }
        }

        // ---- warp-allreduce the sweep's worst off-diagonal; maybe stop
        #pragma unroll
        for (int off = 16; off; off >>= 1)
            mr = fmaxf(mr, __shfl_xor_sync(FULLMASK, mr, off));
        if (mr < CONV_TOL) break;
    }

    // ---- final fresh squared norms -> weights w = log(lambda)/lambda^2
    {
        ull sp = 0ull, sq = 0ull;
        #pragma unroll
        for (int j = 0; j < NP; ++j) {
            sp = fma2(top2[j], top2[j], sp);
            sq = fma2(bot2[j], bot2[j], sq);
        }
        float nt = hsum2(sp);
        float nb = hsum2(sq);
        w[lane]      = 0.5f * logf(fmaxf(nt, 1e-38f)) / nt;
        w[NH + lane] = 0.5f * logf(fmaxf(nb, 1e-38f)) / nb;
    }

    // ---- publish U to shared
    #pragma unroll
    for (int j = 0; j < NP; ++j) {
        float a0, a1, b0, b1;
        unpack2(top2[j], a0, a1);
        unpack2(bot2[j], b0, b1);
        U[2 * j][lane]          = a0;
        U[2 * j + 1][lane]      = a1;
        U[2 * j][NH + lane]     = b0;
        U[2 * j + 1][NH + lane] = b1;
    }
    __syncwarp();

    // ---- out = sum_k w_k u_k u_k^T ; lane computes output columns (2*lane, 2*lane+1)
    #pragma unroll
    for (int j = 0; j < NP; ++j) { top2[j] = 0ull; bot2[j] = 0ull; }
    const int j0 = 2 * lane;
    for (int k = 0; k < N; ++k) {
        float wk = w[k];
        float a0 = wk * U[j0][k];
        float a1 = wk * U[j0 + 1][k];
        ull aa0 = pack2(a0, a0);
        ull aa1 = pack2(a1, a1);
        #pragma unroll
        for (int j = 0; j < NP; ++j) {
            ull vv = pack2(U[2 * j][k], U[2 * j + 1][k]);   // broadcast loads
            top2[j] = fma2(aa0, vv, top2[j]);
            bot2[j] = fma2(aa1, vv, bot2[j]);
        }
    }
    // rows 2j / 2j+1, columns (j0, j0+1) contiguous -> coalesced float2 stores
    #pragma unroll
    for (int j = 0; j < NP; ++j) {
        float t0, t1, b0, b1;
        unpack2(top2[j], t0, t1);
        unpack2(bot2[j], b0, b1);
        *reinterpret_cast<float2*>(o + (2 * j) * N + j0)     = make_float2(t0, b0);
        *reinterpret_cast<float2*>(o + (2 * j + 1) * N + j0) = make_float2(t1, b1);
    }
}

extern "C" void kernel_launch(void* const* d_in, const int* in_sizes, int n_in,
                              void* d_out, int out_size) {
    const float* x = (const float*)d_in[0];
    float* out = (float*)d_out;
    int B = in_sizes[0] / (N * N);   // 8192
    logeig_onesided_kernel<<<B, 32>>>(x, out);
}

// round 11
// speedup vs baseline: 1.8425x; 1.1868x over previous
#include <cuda_runtime.h>
#include <math.h>

#define NSWEEPS_MAX 16
#define N 64
#define NH 32
#define NP 32            // packed row-pairs per column
#define FULLMASK 0xffffffffu
#define CONV_TOL 1e-8f   // on apq^2/(app*aqq); residual error ~ sqrt(tol)/2

typedef unsigned long long ull;

__device__ __forceinline__ ull pack2(float lo, float hi) {
    ull r; asm("mov.b64 %0, {%1, %2};" : "=l"(r) : "f"(lo), "f"(hi)); return r;
}
__device__ __forceinline__ void unpack2(ull v, float& lo, float& hi) {
    asm("mov.b64 {%0, %1}, %2;" : "=f"(lo), "=f"(hi) : "l"(v));
}
__device__ __forceinline__ ull fma2(ull a, ull b, ull c) {
    ull d; asm("fma.rn.f32x2 %0, %1, %2, %3;" : "=l"(d) : "l"(a), "l"(b), "l"(c));
    return d;
}
__device__ __forceinline__ ull mul2(ull a, ull b) {
    ull d; asm("mul.rn.f32x2 %0, %1, %2;" : "=l"(d) : "l"(a), "l"(b));
    return d;
}
__device__ __forceinline__ float hsum2(ull v) {
    float lo, hi; unpack2(v, lo, hi); return lo + hi;
}

// One WARP per 64x64 SPD matrix. One-sided Jacobi on the columns of A.
// Round-10 structure (fresh 3-dot Gram per round, all fp32) with a leaner
// adaptive exit: per-round predicate OR (apq^2 > tol*app*aqq), one
// __any_sync vote per sweep (replaces fdividef+fmax chain+5-shfl reduce;
// frees a live register at the 168-reg cap). Circle-method ring tournament.
//   log(A) = sum_k (log l_k / l_k^2) u_k u_k^T,  l_k^2 = |u_k|^2.
__global__ void __launch_bounds__(32, 12)
logeig_onesided_kernel(const float* __restrict__ x, float* __restrict__ out)
{
    __shared__ float U[N][N + 1];
    __shared__ float w[N];

    const int lane = threadIdx.x;
    const size_t base = (size_t)blockIdx.x * (N * N);
    const float* __restrict__ xin = x + base;
    float* __restrict__ o = out + base;

    ull top2[NP], bot2[NP];   // columns in slots (lane) and (32+lane)

    // Load: top2[j] packs rows (2j, 2j+1) of column `lane`
    #pragma unroll
    for (int j = 0; j < NP; ++j) {
        top2[j] = pack2(xin[(2 * j) * N + lane],      xin[(2 * j + 1) * N + lane]);
        bot2[j] = pack2(xin[(2 * j) * N + NH + lane], xin[(2 * j + 1) * N + NH + lane]);
    }

    for (int sweep = 0; sweep < NSWEEPS_MAX; ++sweep) {
        bool bad = false;   // any pair this sweep above tolerance?
        for (int r = 0; r < N - 1; ++r) {
            // ---- fresh 2x2 Gram block of the owned pair (fused 3-dot)
            ull sp = 0ull, sx = 0ull, sq = 0ull;
            #pragma unroll
            for (int j = 0; j < NP; ++j) {
                ull t2 = top2[j], b2 = bot2[j];
                sp = fma2(t2, t2, sp);
                sx = fma2(t2, b2, sx);
                sq = fma2(b2, b2, sq);
            }
            float app = hsum2(sp);
            float apq = hsum2(sx);
            float aqq = hsum2(sq);

            bad = bad || (apq * apq > CONV_TOL * (app * aqq));

            // ---- Jacobi rotation from the Gram block
            float c = 1.0f, s = 0.0f;
            if (fabsf(apq) > 1e-30f) {
                float theta = 0.5f * (aqq - app) / apq;
                float t = copysignf(1.0f, theta) /
                          (fabsf(theta) + sqrtf(fmaf(theta, theta, 1.0f)));
                c = rsqrtf(fmaf(t, t, 1.0f));
                s = t * c;
            }
            const ull cc = pack2(c, c);
            const ull ss = pack2(s, s);
            const ull ns = pack2(-s, -s);

            // ---- rotate the column pair and ring-shift columns across lanes
            // (circle-method tournament, fused). Rows never move.
            #pragma unroll
            for (int j = 0; j < NP; ++j) {
                ull t2 = top2[j], b2 = bot2[j];
                ull rt = fma2(cc, t2, mul2(ns, b2));    // c*top - s*bot
                ull rb = fma2(ss, t2, mul2(cc, b2));    // s*top + c*bot
                ull tsel = (lane == 0) ? rb : rt;
                ull tup  = __shfl_up_sync(FULLMASK, tsel, 1);
                top2[j]  = (lane == 0) ? rt : tup;
                ull bdn  = __shfl_down_sync(FULLMASK, rb, 1);
                bot2[j]  = (lane == 31) ? rt : bdn;
            }
        }

        // ---- one vote per sweep: stop when every pair was below tolerance
        if (!__any_sync(FULLMASK, bad)) break;
    }

    // ---- final fresh squared norms -> weights w = log(lambda)/lambda^2
    {
        ull sp = 0ull, sq = 0ull;
        #pragma unroll
        for (int j = 0; j < NP; ++j) {
            sp = fma2(top2[j], top2[j], sp);
            sq = fma2(bot2[j], bot2[j], sq);
        }
        float nt = hsum2(sp);
        float nb = hsum2(sq);
        w[lane]      = 0.5f * logf(fmaxf(nt, 1e-38f)) / nt;
        w[NH + lane] = 0.5f * logf(fmaxf(nb, 1e-38f)) / nb;
    }

    // ---- publish U to shared
    #pragma unroll
    for (int j = 0; j < NP; ++j) {
        float a0, a1, b0, b1;
        unpack2(top2[j], a0, a1);
        unpack2(bot2[j], b0, b1);
        U[2 * j][lane]          = a0;
        U[2 * j + 1][lane]      = a1;
        U[2 * j][NH + lane]     = b0;
        U[2 * j + 1][NH + lane] = b1;
    }
    __syncwarp();

    // ---- out = sum_k w_k u_k u_k^T ; lane computes output columns (2*lane, 2*lane+1)
    #pragma unroll
    for (int j = 0; j < NP; ++j) { top2[j] = 0ull; bot2[j] = 0ull; }
    const int j0 = 2 * lane;
    for (int k = 0; k < N; ++k) {
        float wk = w[k];
        float a0 = wk * U[j0][k];
        float a1 = wk * U[j0 + 1][k];
        ull aa0 = pack2(a0, a0);
        ull aa1 = pack2(a1, a1);
        #pragma unroll
        for (int j = 0; j < NP; ++j) {
            ull vv = pack2(U[2 * j][k], U[2 * j + 1][k]);   // broadcast loads
            top2[j] = fma2(aa0, vv, top2[j]);
            bot2[j] = fma2(aa1, vv, bot2[j]);
        }
    }
    // rows 2j / 2j+1, columns (j0, j0+1) contiguous -> coalesced float2 stores
    #pragma unroll
    for (int j = 0; j < NP; ++j) {
        float t0, t1, b0, b1;
        unpack2(top2[j], t0, t1);
        unpack2(bot2[j], b0, b1);
        *reinterpret_cast<float2*>(o + (2 * j) * N + j0)     = make_float2(t0, b0);
        *reinterpret_cast<float2*>(o + (2 * j + 1) * N + j0) = make_float2(t1, b1);
    }
}

extern "C" void kernel_launch(void* const* d_in, const int* in_sizes, int n_in,
                              void* d_out, int out_size) {
    const float* x = (const float*)d_in[0];
    float* out = (float*)d_out;
    int B = in_sizes[0] / (N * N);   // 8192
    logeig_onesided_kernel<<<B, 32>>>(x, out);
}

// round 12
// speedup vs baseline: 2.1058x; 1.1429x over previous
#include <cuda_runtime.h>
#include <math.h>

#define NSWEEPS_MAX 16
#define N 64
#define NH 32
#define NP 32            // packed row-pairs per column
#define FULLMASK 0xffffffffu
#define CONV_TOL 1e-8f   // on apq^2/(app*aqq); residual error ~ sqrt(tol)/2

typedef unsigned long long ull;

__device__ __forceinline__ ull pack2(float lo, float hi) {
    ull r; asm("mov.b64 %0, {%1, %2};" : "=l"(r) : "f"(lo), "f"(hi)); return r;
}
__device__ __forceinline__ void unpack2(ull v, float& lo, float& hi) {
    asm("mov.b64 {%0, %1}, %2;" : "=f"(lo), "=f"(hi) : "l"(v));
}
__device__ __forceinline__ ull fma2(ull a, ull b, ull c) {
    ull d; asm("fma.rn.f32x2 %0, %1, %2, %3;" : "=l"(d) : "l"(a), "l"(b), "l"(c));
    return d;
}
__device__ __forceinline__ ull mul2(ull a, ull b) {
    ull d; asm("mul.rn.f32x2 %0, %1, %2;" : "=l"(d) : "l"(a), "l"(b));
    return d;
}
__device__ __forceinline__ float hsum2(ull v) {
    float lo, hi; unpack2(v, lo, hi); return lo + hi;
}

// One WARP per 64x64 SPD matrix. One-sided Jacobi on the columns of A.
// Gram fusion, fp32-only (round 8's fp64 variant spilled; fp32 adds just 2
// live regs): next round's apq is accumulated inside the rotation loop on the
// post-shift columns; app/aqq maintained by the exact update app' = app-t*apq
// (feeds only theta + the convergence check, both insensitive to its
// cancellation error) and resynced FRESH at every sweep start. Fast-approx
// divide for theta (t->0 limit is exact; Jacobi is self-correcting).
// Adaptive exit: per-round predicate OR, one __any_sync per sweep.
//   log(A) = sum_k (log l_k / l_k^2) u_k u_k^T,  l_k^2 = |u_k|^2.
__global__ void __launch_bounds__(32, 12)
logeig_onesided_kernel(const float* __restrict__ x, float* __restrict__ out)
{
    __shared__ float U[N][N + 1];
    __shared__ float w[N];

    const int lane = threadIdx.x;
    const size_t base = (size_t)blockIdx.x * (N * N);
    const float* __restrict__ xin = x + base;
    float* __restrict__ o = out + base;

    ull top2[NP], bot2[NP];   // columns in slots (lane) and (32+lane)

    // Load: top2[j] packs rows (2j, 2j+1) of column `lane`
    #pragma unroll
    for (int j = 0; j < NP; ++j) {
        top2[j] = pack2(xin[(2 * j) * N + lane],      xin[(2 * j + 1) * N + lane]);
        bot2[j] = pack2(xin[(2 * j) * N + NH + lane], xin[(2 * j + 1) * N + NH + lane]);
    }

    for (int sweep = 0; sweep < NSWEEPS_MAX; ++sweep) {
        // ---- fresh full Gram of the owned pair at sweep start (resync)
        float app, apq, aqq;
        {
            ull sp = 0ull, sx = 0ull, sq = 0ull;
            #pragma unroll
            for (int j = 0; j < NP; ++j) {
                ull t2 = top2[j], b2 = bot2[j];
                sp = fma2(t2, t2, sp);
                sx = fma2(t2, b2, sx);
                sq = fma2(b2, b2, sq);
            }
            app = hsum2(sp);
            apq = hsum2(sx);
            aqq = hsum2(sq);
        }

        bool bad = false;   // any pair this sweep above tolerance?
        for (int r = 0; r < N - 1; ++r) {
            bad = bad || (apq * apq > CONV_TOL * (app * aqq));

            // ---- Jacobi rotation from the 2x2 Gram
            float c = 1.0f, s = 0.0f, t = 0.0f;
            if (fabsf(apq) > 1e-30f) {
                float theta = __fdividef(0.5f * (aqq - app), apq);
                t = copysignf(1.0f, theta) /
                    (fabsf(theta) + sqrtf(fmaf(theta, theta, 1.0f)));
                c = rsqrtf(fmaf(t, t, 1.0f));
                s = t * c;
            }
            const ull cc = pack2(c, c);
            const ull ss = pack2(s, s);
            const ull ns = pack2(-s, -s);

            // ---- rotate + ring-shift columns across lanes (circle method),
            //      fusing next round's apq on the post-shift pair
            ull sxn = 0ull;
            #pragma unroll
            for (int j = 0; j < NP; ++j) {
                ull t2 = top2[j], b2 = bot2[j];
                ull rt = fma2(cc, t2, mul2(ns, b2));    // c*top - s*bot
                ull rb = fma2(ss, t2, mul2(cc, b2));    // s*top + c*bot
                ull tsel = (lane == 0) ? rb : rt;
                ull tup  = __shfl_up_sync(FULLMASK, tsel, 1);
                ull ntv  = (lane == 0) ? rt : tup;
                ull bdn  = __shfl_down_sync(FULLMASK, rb, 1);
                ull nbv  = (lane == 31) ? rt : bdn;
                top2[j] = ntv;
                bot2[j] = nbv;
                sxn = fma2(ntv, nbv, sxn);
            }

            // ---- maintained norms (exact identity) + same ring shift
            float app2 = fmaf(-t, apq, app);
            float aqq2 = fmaf( t, apq, aqq);
            float nsel = (lane == 0) ? aqq2 : app2;
            float nup  = __shfl_up_sync(FULLMASK, nsel, 1);
            app        = (lane == 0) ? app2 : nup;
            float ndn  = __shfl_down_sync(FULLMASK, aqq2, 1);
            aqq        = (lane == 31) ? app2 : ndn;

            apq = hsum2(sxn);
        }

        // ---- one vote per sweep: stop when every pair was below tolerance
        if (!__any_sync(FULLMASK, bad)) break;
    }

    // ---- final fresh squared norms -> weights w = log(lambda)/lambda^2
    {
        ull sp = 0ull, sq = 0ull;
        #pragma unroll
        for (int j = 0; j < NP; ++j) {
            sp = fma2(top2[j], top2[j], sp);
            sq = fma2(bot2[j], bot2[j], sq);
        }
        float nt = hsum2(sp);
        float nb = hsum2(sq);
        w[lane]      = 0.5f * logf(fmaxf(nt, 1e-38f)) / nt;
        w[NH + lane] = 0.5f * logf(fmaxf(nb, 1e-38f)) / nb;
    }

    // ---- publish U to shared
    #pragma unroll
    for (int j = 0; j < NP; ++j) {
        float a0, a1, b0, b1;
        unpack2(top2[j], a0, a1);
        unpack2(bot2[j], b0, b1);
        U[2 * j][lane]          = a0;
        U[2 * j + 1][lane]      = a1;
        U[2 * j][NH + lane]     = b0;
        U[2 * j + 1][NH + lane] = b1;
    }
    __syncwarp();

    // ---- out = sum_k w_k u_k u_k^T ; lane computes output columns (2*lane, 2*lane+1)
    #pragma unroll
    for (int j = 0; j < NP; ++j) { top2[j] = 0ull; bot2[j] = 0ull; }
    const int j0 = 2 * lane;
    for (int k = 0; k < N; ++k) {
        float wk = w[k];
        float a0 = wk * U[j0][k];
        float a1 = wk * U[j0 + 1][k];
        ull aa0 = pack2(a0, a0);
        ull aa1 = pack2(a1, a1);
        #pragma unroll
        for (int j = 0; j < NP; ++j) {
            ull vv = pack2(U[2 * j][k], U[2 * j + 1][k]);   // broadcast loads
            top2[j] = fma2(aa0, vv, top2[j]);
            bot2[j] = fma2(aa1, vv, bot2[j]);
        }
    }
    // rows 2j / 2j+1, columns (j0, j0+1) contiguous -> coalesced float2 stores
    #pragma unroll
    for (int j = 0; j < NP; ++j) {
        float t0, t1, b0, b1;
        unpack2(top2[j], t0, t1);
        unpack2(bot2[j], b0, b1);
        *reinterpret_cast<float2*>(o + (2 * j) * N + j0)     = make_float2(t0, b0);
        *reinterpret_cast<float2*>(o + (2 * j + 1) * N + j0) = make_float2(t1, b1);
    }
}

extern "C" void kernel_launch(void* const* d_in, const int* in_sizes, int n_in,
                              void* d_out, int out_size) {
    const float* x = (const float*)d_in[0];
    float* out = (float*)d_out;
    int B = in_sizes[0] / (N * N);   // 8192
    logeig_onesided_kernel<<<B, 32>>>(x, out);
}